// round 1
// baseline (speedup 1.0000x reference)
#include <cuda_runtime.h>
#include <math.h>

#define SEQ   4096
#define DIM   1024
#define OUTD  2048
#define SCALE 0.03125f   // 1/sqrt(1024)

// Scratch (no allocations allowed in kernel_launch)
__device__ float g_q[(size_t)SEQ * DIM];
__device__ float g_k[(size_t)SEQ * DIM];
__device__ float g_v[(size_t)SEQ * DIM];
__device__ float g_p[(size_t)SEQ * SEQ];

constexpr int BM = 128, BN = 128, BK = 16;
constexpr int TM = 8,  TN = 8;

// ---------------------------------------------------------------------------
// QKV projection: Y = x @ W + b for (Q, K, V) selected by blockIdx.z
// ---------------------------------------------------------------------------
__global__ __launch_bounds__(256) void qkv_kernel(
    const float* __restrict__ x,
    const float* __restrict__ Wq, const float* __restrict__ bq,
    const float* __restrict__ Wk, const float* __restrict__ bk,
    const float* __restrict__ Wv, const float* __restrict__ bv)
{
    const float* W; const float* bias; float* Y;
    if (blockIdx.z == 0)      { W = Wq; bias = bq; Y = g_q; }
    else if (blockIdx.z == 1) { W = Wk; bias = bk; Y = g_k; }
    else                      { W = Wv; bias = bv; Y = g_v; }

    __shared__ float As[BK][BM + 4];
    __shared__ float Bs[BK][BN];

    int tid = threadIdx.x;
    int tx = tid & 15, ty = tid >> 4;
    int row0 = blockIdx.y * BM;
    int col0 = blockIdx.x * BN;

    float acc[TM][TN];
#pragma unroll
    for (int i = 0; i < TM; i++)
#pragma unroll
        for (int j = 0; j < TN; j++) acc[i][j] = 0.f;

    for (int k0 = 0; k0 < DIM; k0 += BK) {
        // A tile: 128 rows x 16 k (transposed store into As[k][m])
#pragma unroll
        for (int l = 0; l < 2; l++) {
            int idx = tid + l * 256;
            int r = idx >> 2;
            int c = (idx & 3) * 4;
            float4 v = *(const float4*)&x[(size_t)(row0 + r) * DIM + k0 + c];
            As[c + 0][r] = v.x; As[c + 1][r] = v.y;
            As[c + 2][r] = v.z; As[c + 3][r] = v.w;
        }
        // B tile: 16 k x 128 n (direct copy)
#pragma unroll
        for (int l = 0; l < 2; l++) {
            int idx = tid + l * 256;
            int r = idx >> 5;
            int c = (idx & 31) * 4;
            *(float4*)&Bs[r][c] = *(const float4*)&W[(size_t)(k0 + r) * DIM + col0 + c];
        }
        __syncthreads();
#pragma unroll
        for (int kk = 0; kk < BK; kk++) {
            float a[TM], b[TN];
            *(float4*)&a[0] = *(const float4*)&As[kk][ty * TM];
            *(float4*)&a[4] = *(const float4*)&As[kk][ty * TM + 4];
            *(float4*)&b[0] = *(const float4*)&Bs[kk][tx * TN];
            *(float4*)&b[4] = *(const float4*)&Bs[kk][tx * TN + 4];
#pragma unroll
            for (int i = 0; i < TM; i++)
#pragma unroll
                for (int j = 0; j < TN; j++) acc[i][j] += a[i] * b[j];
        }
        __syncthreads();
    }
#pragma unroll
    for (int i = 0; i < TM; i++) {
        int r = row0 + ty * TM + i;
#pragma unroll
        for (int j = 0; j < TN; j += 4) {
            int c = col0 + tx * TN + j;
            float4 v;
            v.x = acc[i][j + 0] + bias[c + 0];
            v.y = acc[i][j + 1] + bias[c + 1];
            v.z = acc[i][j + 2] + bias[c + 2];
            v.w = acc[i][j + 3] + bias[c + 3];
            *(float4*)&Y[(size_t)r * DIM + c] = v;
        }
    }
}

// ---------------------------------------------------------------------------
// scores = scale * Q @ K^T, upper-triangular tiles only (mask keeps j >= i)
// ---------------------------------------------------------------------------
__global__ __launch_bounds__(256) void scores_kernel()
{
    int bi = blockIdx.y, bj = blockIdx.x;
    if (bj < bi) return;   // fully-masked tile: never written, never read

    __shared__ float As[BK][BM + 4];
    __shared__ float Bs[BK][BN + 4];

    int tid = threadIdx.x;
    int tx = tid & 15, ty = tid >> 4;
    int row0 = bi * BM;
    int col0 = bj * BN;

    float acc[TM][TN];
#pragma unroll
    for (int i = 0; i < TM; i++)
#pragma unroll
        for (int j = 0; j < TN; j++) acc[i][j] = 0.f;

    for (int k0 = 0; k0 < DIM; k0 += BK) {
#pragma unroll
        for (int l = 0; l < 2; l++) {
            int idx = tid + l * 256;
            int r = idx >> 2;
            int c = (idx & 3) * 4;
            float4 v = *(const float4*)&g_q[(size_t)(row0 + r) * DIM + k0 + c];
            As[c + 0][r] = v.x; As[c + 1][r] = v.y;
            As[c + 2][r] = v.z; As[c + 3][r] = v.w;
            float4 w = *(const float4*)&g_k[(size_t)(col0 + r) * DIM + k0 + c];
            Bs[c + 0][r] = w.x; Bs[c + 1][r] = w.y;
            Bs[c + 2][r] = w.z; Bs[c + 3][r] = w.w;
        }
        __syncthreads();
#pragma unroll
        for (int kk = 0; kk < BK; kk++) {
            float a[TM], b[TN];
            *(float4*)&a[0] = *(const float4*)&As[kk][ty * TM];
            *(float4*)&a[4] = *(const float4*)&As[kk][ty * TM + 4];
            *(float4*)&b[0] = *(const float4*)&Bs[kk][tx * TN];
            *(float4*)&b[4] = *(const float4*)&Bs[kk][tx * TN + 4];
#pragma unroll
            for (int i = 0; i < TM; i++)
#pragma unroll
                for (int j = 0; j < TN; j++) acc[i][j] += a[i] * b[j];
        }
        __syncthreads();
    }
#pragma unroll
    for (int i = 0; i < TM; i++) {
        int r = row0 + ty * TM + i;
#pragma unroll
        for (int j = 0; j < TN; j += 4) {
            int c = col0 + tx * TN + j;
            float4 v;
            v.x = acc[i][j + 0] * SCALE;
            v.y = acc[i][j + 1] * SCALE;
            v.z = acc[i][j + 2] * SCALE;
            v.w = acc[i][j + 3] * SCALE;
            *(float4*)&g_p[(size_t)r * SEQ + c] = v;
        }
    }
}

// ---------------------------------------------------------------------------
// Row softmax over j >= i; zero-fill masked strip inside the diagonal tile
// so the PV GEMM can start its k-loop at the diagonal tile boundary.
// ---------------------------------------------------------------------------
__global__ __launch_bounds__(256) void softmax_kernel()
{
    int i = blockIdx.x;
    int t = threadIdx.x;
    float* row = g_p + (size_t)i * SEQ;

    float vals[16];
    float m = -INFINITY;
#pragma unroll
    for (int c = 0; c < 16; c++) {
        int j = t + (c << 8);
        float v = (j >= i) ? row[j] : -INFINITY;
        vals[c] = v;
        m = fmaxf(m, v);
    }

    __shared__ float red[8];
#pragma unroll
    for (int o = 16; o > 0; o >>= 1) m = fmaxf(m, __shfl_xor_sync(0xffffffffu, m, o));
    if ((t & 31) == 0) red[t >> 5] = m;
    __syncthreads();
    float mm = red[0];
#pragma unroll
    for (int w = 1; w < 8; w++) mm = fmaxf(mm, red[w]);
    __syncthreads();

    float sum = 0.f;
#pragma unroll
    for (int c = 0; c < 16; c++) {
        float e = (vals[c] > -INFINITY) ? __expf(vals[c] - mm) : 0.f;
        vals[c] = e;
        sum += e;
    }
#pragma unroll
    for (int o = 16; o > 0; o >>= 1) sum += __shfl_xor_sync(0xffffffffu, sum, o);
    if ((t & 31) == 0) red[t >> 5] = sum;
    __syncthreads();
    float tot = 0.f;
#pragma unroll
    for (int w = 0; w < 8; w++) tot += red[w];
    float inv = 1.0f / tot;

    int rowstart = i & ~(BM - 1);
#pragma unroll
    for (int c = 0; c < 16; c++) {
        int j = t + (c << 8);
        if (j >= i)             row[j] = vals[c] * inv;
        else if (j >= rowstart) row[j] = 0.f;   // masked strip in diagonal tile
    }
}

// ---------------------------------------------------------------------------
// read = probs @ V ; k-loop starts at the diagonal tile (probs below are 0 /
// never written). Writes into out[:, 1024:2048].
// ---------------------------------------------------------------------------
__global__ __launch_bounds__(256) void pv_kernel(float* __restrict__ out)
{
    int bi = blockIdx.y;
    int row0 = bi * BM;
    int col0 = blockIdx.x * BN;

    __shared__ float As[BK][BM + 4];
    __shared__ float Bs[BK][BN];

    int tid = threadIdx.x;
    int tx = tid & 15, ty = tid >> 4;

    float acc[TM][TN];
#pragma unroll
    for (int i = 0; i < TM; i++)
#pragma unroll
        for (int j = 0; j < TN; j++) acc[i][j] = 0.f;

    for (int k0 = row0; k0 < SEQ; k0 += BK) {
#pragma unroll
        for (int l = 0; l < 2; l++) {
            int idx = tid + l * 256;
            int r = idx >> 2;
            int c = (idx & 3) * 4;
            float4 v = *(const float4*)&g_p[(size_t)(row0 + r) * SEQ + k0 + c];
            As[c + 0][r] = v.x; As[c + 1][r] = v.y;
            As[c + 2][r] = v.z; As[c + 3][r] = v.w;
        }
#pragma unroll
        for (int l = 0; l < 2; l++) {
            int idx = tid + l * 256;
            int r = idx >> 5;
            int c = (idx & 31) * 4;
            *(float4*)&Bs[r][c] = *(const float4*)&g_v[(size_t)(k0 + r) * DIM + col0 + c];
        }
        __syncthreads();
#pragma unroll
        for (int kk = 0; kk < BK; kk++) {
            float a[TM], b[TN];
            *(float4*)&a[0] = *(const float4*)&As[kk][ty * TM];
            *(float4*)&a[4] = *(const float4*)&As[kk][ty * TM + 4];
            *(float4*)&b[0] = *(const float4*)&Bs[kk][tx * TN];
            *(float4*)&b[4] = *(const float4*)&Bs[kk][tx * TN + 4];
#pragma unroll
            for (int i = 0; i < TM; i++)
#pragma unroll
                for (int j = 0; j < TN; j++) acc[i][j] += a[i] * b[j];
        }
        __syncthreads();
    }
#pragma unroll
    for (int i = 0; i < TM; i++) {
        int r = row0 + ty * TM + i;
#pragma unroll
        for (int j = 0; j < TN; j += 4) {
            int c = col0 + tx * TN + j;
            float4 v;
            v.x = acc[i][j + 0]; v.y = acc[i][j + 1];
            v.z = acc[i][j + 2]; v.w = acc[i][j + 3];
            *(float4*)&out[(size_t)r * OUTD + DIM + c] = v;
        }
    }
}

// ---------------------------------------------------------------------------
// out[:, 0:1024] = x
// ---------------------------------------------------------------------------
__global__ __launch_bounds__(256) void copy_x_kernel(const float* __restrict__ x,
                                                     float* __restrict__ out)
{
    int idx = blockIdx.x * blockDim.x + threadIdx.x;  // float4 index
    int r = idx >> 8;          // 256 float4 per row
    int c = (idx & 255) * 4;
    *(float4*)&out[(size_t)r * OUTD + c] = *(const float4*)&x[(size_t)r * DIM + c];
}

// ---------------------------------------------------------------------------
extern "C" void kernel_launch(void* const* d_in, const int* in_sizes, int n_in,
                              void* d_out, int out_size)
{
    const float* x  = (const float*)d_in[0];
    const float* Wk = (const float*)d_in[1];
    const float* bk = (const float*)d_in[2];
    const float* Wq = (const float*)d_in[3];
    const float* bq = (const float*)d_in[4];
    const float* Wv = (const float*)d_in[5];
    const float* bv = (const float*)d_in[6];
    float* out = (float*)d_out;

    dim3 gQKV(DIM / BN, SEQ / BM, 3);
    qkv_kernel<<<gQKV, 256>>>(x, Wq, bq, Wk, bk, Wv, bv);

    dim3 gS(SEQ / BN, SEQ / BM);
    scores_kernel<<<gS, 256>>>();

    softmax_kernel<<<SEQ, 256>>>();

    dim3 gPV(DIM / BN, SEQ / BM);
    pv_kernel<<<gPV, 256>>>(out);

    copy_x_kernel<<<SEQ, 256>>>(x, out);
}

// round 3
// speedup vs baseline: 2.3016x; 2.3016x over previous
#include <cuda_runtime.h>
#include <math.h>
#include <stdint.h>

#define SEQ   4096
#define DIM   1024
#define OUTD  2048
#define SCALE 0.03125f   // 1/sqrt(1024)

#define PADW  36                       // 32 floats + 4 pad per smem row
#define BUF_B (128 * PADW * 4)         // one operand tile: 18432 B
#define STAGE (2 * BUF_B)              // A + B per stage: 36864 B
#define SMEM_DYN (2 * STAGE)           // double buffered: 73728 B

// ---------------------------------------------------------------------------
// scratch (__device__ globals; no allocations allowed)
// ---------------------------------------------------------------------------
__device__ float g_x [(size_t)SEQ * DIM];          // x, tf32-rounded
__device__ float g_wt[(size_t)3 * DIM * DIM];      // W^T (Q,K,V), tf32-rounded
__device__ float g_q [(size_t)SEQ * DIM];          // tf32-rounded
__device__ float g_k [(size_t)SEQ * DIM];          // tf32-rounded
__device__ float g_vt[(size_t)DIM * SEQ];          // V^T [d][s], tf32-rounded
__device__ float g_s [(size_t)SEQ * SEQ];          // scores fp32
__device__ float g_p [(size_t)SEQ * SEQ];          // probs, tf32-rounded

// ---------------------------------------------------------------------------
// helpers
// ---------------------------------------------------------------------------
__device__ __forceinline__ uint32_t smem_u32(const void* p) {
    uint32_t a;
    asm("{ .reg .u64 t; cvta.to.shared.u64 t, %1; cvt.u32.u64 %0, t; }" : "=r"(a) : "l"(p));
    return a;
}
__device__ __forceinline__ float tf32r(float x) {
    uint32_t u;
    asm("cvt.rna.tf32.f32 %0, %1;" : "=r"(u) : "f"(x));
    return __uint_as_float(u);
}
__device__ __forceinline__ void cp16(uint32_t s, const float* g) {
    asm volatile("{ .reg .u64 gg; cvta.to.global.u64 gg, %1;"
                 "  cp.async.cg.shared.global [%0], [gg], 16; }"
                 :: "r"(s), "l"(g));
}
#define CP_COMMIT() asm volatile("cp.async.commit_group;" ::: "memory")
#define CP_WAIT1()  asm volatile("cp.async.wait_group 1;"  ::: "memory")

__device__ __forceinline__ void mma8(float* d, const float* a, const float* b) {
    asm volatile(
        "mma.sync.aligned.m16n8k8.row.col.f32.tf32.tf32.f32 "
        "{%0,%1,%2,%3}, {%4,%5,%6,%7}, {%8,%9}, {%0,%1,%2,%3};"
        : "+f"(d[0]), "+f"(d[1]), "+f"(d[2]), "+f"(d[3])
        : "r"(__float_as_uint(a[0])), "r"(__float_as_uint(a[1])),
          "r"(__float_as_uint(a[2])), "r"(__float_as_uint(a[3])),
          "r"(__float_as_uint(b[0])), "r"(__float_as_uint(b[1])));
}

// ---------------------------------------------------------------------------
// shared mainloop: acc[4][4][4] += A[128,K] * B[128,K]^T over k in [kbeg,kend)
// A: [m][k] row-major (lda), rows arow0.. ; B: [n][k] row-major (ldb), rows brow0..
// warp layout: 8 warps = 2(m) x 4(n); warp tile 64x32; m16n8k8 tf32 tiles 4x4
// ---------------------------------------------------------------------------
__device__ __forceinline__ void gemm_mainloop(
    float acc[4][4][4], char* smem,
    const float* __restrict__ Ag, int lda, int arow0,
    const float* __restrict__ Bg, int ldb, int brow0,
    int kbeg, int kend)
{
    const int tid  = threadIdx.x;
    const int wid  = tid >> 5, lane = tid & 31;
    const int wm   = (wid & 1) * 64;
    const int wn   = (wid >> 1) * 32;
    const int r    = lane >> 2, cc = lane & 3;
    const uint32_t sA = smem_u32(smem);
    const int nch = (kend - kbeg) >> 5;

    const int lm = tid >> 1;                 // loader: row index (2 threads/row)
    const int lq0 = (tid & 1) * 4;           // loader: starting 16B-chunk (of 8)

    // prologue: fill both stages
#pragma unroll
    for (int c = 0; c < 2; c++) {
        if (c < nch) {
            int k0 = kbeg + c * 32;
            uint32_t st = sA + c * STAGE;
#pragma unroll
            for (int q = 0; q < 4; q++) {
                cp16(st +         (lm * PADW + (lq0 + q) * 4) * 4,
                     Ag + (size_t)(arow0 + lm) * lda + k0 + (lq0 + q) * 4);
                cp16(st + BUF_B + (lm * PADW + (lq0 + q) * 4) * 4,
                     Bg + (size_t)(brow0 + lm) * ldb + k0 + (lq0 + q) * 4);
            }
        }
        CP_COMMIT();
    }

    for (int c = 0; c < nch; c++) {
        CP_WAIT1();
        __syncthreads();
        const float* As = (const float*)(smem + (c & 1) * STAGE);
        const float* Bs = (const float*)(smem + (c & 1) * STAGE + BUF_B);
#pragma unroll
        for (int ks = 0; ks < 4; ks++) {
            float a[4][4], b[4][2];
#pragma unroll
            for (int mt = 0; mt < 4; mt++) {
                const float* p = As + (wm + mt * 16 + r) * PADW + ks * 8 + cc;
                a[mt][0] = p[0];
                a[mt][1] = p[8 * PADW];
                a[mt][2] = p[4];
                a[mt][3] = p[8 * PADW + 4];
            }
#pragma unroll
            for (int nt = 0; nt < 4; nt++) {
                const float* p = Bs + (wn + nt * 8 + r) * PADW + ks * 8 + cc;
                b[nt][0] = p[0];
                b[nt][1] = p[4];
            }
#pragma unroll
            for (int mt = 0; mt < 4; mt++)
#pragma unroll
                for (int nt = 0; nt < 4; nt++)
                    mma8(acc[mt][nt], a[mt], b[nt]);
        }
        __syncthreads();
        // refill the stage we just consumed with chunk c+2
        if (c + 2 < nch) {
            int k0 = kbeg + (c + 2) * 32;
            uint32_t st = sA + (c & 1) * STAGE;
#pragma unroll
            for (int q = 0; q < 4; q++) {
                cp16(st +         (lm * PADW + (lq0 + q) * 4) * 4,
                     Ag + (size_t)(arow0 + lm) * lda + k0 + (lq0 + q) * 4);
                cp16(st + BUF_B + (lm * PADW + (lq0 + q) * 4) * 4,
                     Bg + (size_t)(brow0 + lm) * ldb + k0 + (lq0 + q) * 4);
            }
        }
        CP_COMMIT();
    }
}

#define GEMM_THREAD_COORDS()                                   \
    const int tid = threadIdx.x;                               \
    const int wid = tid >> 5, lane = tid & 31;                 \
    const int wm = (wid & 1) * 64, wn = (wid >> 1) * 32;       \
    const int r = lane >> 2, cc = lane & 3;

// ---------------------------------------------------------------------------
// QKV: z=0: Q = x@Wq^T' + bq ; z=1: K ; z=2: V^T = Wvt @ x^T + bv(row)
// ---------------------------------------------------------------------------
__global__ __launch_bounds__(256) void gemm_qkv_kernel(
    const float* __restrict__ bq, const float* __restrict__ bk, const float* __restrict__ bv)
{
    const int z = blockIdx.z;
    if (z < 2 && blockIdx.x >= 8) return;   // n = 1024 only
    if (z == 2 && blockIdx.y >= 8) return;  // m = 1024 only

    extern __shared__ char smem[];
    const int row0 = blockIdx.y * 128, col0 = blockIdx.x * 128;

    float acc[4][4][4];
#pragma unroll
    for (int i = 0; i < 4; i++)
#pragma unroll
        for (int j = 0; j < 4; j++)
#pragma unroll
            for (int q = 0; q < 4; q++) acc[i][j][q] = 0.f;

    const float *Ag, *Bg, *bias;
    if (z == 0)      { Ag = g_x;               Bg = g_wt;               bias = bq; }
    else if (z == 1) { Ag = g_x;               Bg = g_wt + DIM * DIM;   bias = bk; }
    else             { Ag = g_wt + 2 * DIM * DIM; Bg = g_x;             bias = bv; }

    gemm_mainloop(acc, smem, Ag, DIM, row0, Bg, DIM, col0, 0, DIM);

    GEMM_THREAD_COORDS();
    float* dst; size_t ld;
    if (z == 0)      { dst = g_q;  ld = DIM; }
    else if (z == 1) { dst = g_k;  ld = DIM; }
    else             { dst = g_vt; ld = SEQ; }

#pragma unroll
    for (int mt = 0; mt < 4; mt++)
#pragma unroll
        for (int h = 0; h < 2; h++) {
            int m = row0 + wm + mt * 16 + r + 8 * h;
            float brow = (z == 2) ? bias[m] : 0.f;
#pragma unroll
            for (int nt = 0; nt < 4; nt++) {
                int n = col0 + wn + nt * 8 + 2 * cc;
                float v0 = acc[mt][nt][2 * h + 0] + ((z == 2) ? brow : bias[n]);
                float v1 = acc[mt][nt][2 * h + 1] + ((z == 2) ? brow : bias[n + 1]);
                float2 w = make_float2(tf32r(v0), tf32r(v1));
                *(float2*)&dst[(size_t)m * ld + n] = w;
            }
        }
}

// ---------------------------------------------------------------------------
// scores: S = SCALE * Q K^T, upper-triangular tiles only
// ---------------------------------------------------------------------------
__global__ __launch_bounds__(256) void gemm_scores_kernel()
{
    const int bi = blockIdx.y, bj = blockIdx.x;
    if (bj < bi) return;

    extern __shared__ char smem[];
    const int row0 = bi * 128, col0 = bj * 128;

    float acc[4][4][4];
#pragma unroll
    for (int i = 0; i < 4; i++)
#pragma unroll
        for (int j = 0; j < 4; j++)
#pragma unroll
            for (int q = 0; q < 4; q++) acc[i][j][q] = 0.f;

    gemm_mainloop(acc, smem, g_q, DIM, row0, g_k, DIM, col0, 0, DIM);

    GEMM_THREAD_COORDS();
#pragma unroll
    for (int mt = 0; mt < 4; mt++)
#pragma unroll
        for (int h = 0; h < 2; h++) {
            int m = row0 + wm + mt * 16 + r + 8 * h;
#pragma unroll
            for (int nt = 0; nt < 4; nt++) {
                int n = col0 + wn + nt * 8 + 2 * cc;
                float2 w = make_float2(acc[mt][nt][2 * h] * SCALE,
                                       acc[mt][nt][2 * h + 1] * SCALE);
                *(float2*)&g_s[(size_t)m * SEQ + n] = w;
            }
        }
}

// ---------------------------------------------------------------------------
// softmax over j >= i; writes tf32-rounded probs, zero strip in diagonal tile
// ---------------------------------------------------------------------------
__global__ __launch_bounds__(256) void softmax_kernel()
{
    const int i = blockIdx.x;
    const int t = threadIdx.x;
    const float* row = g_s + (size_t)i * SEQ;

    float vals[16];
    float m = -INFINITY;
#pragma unroll
    for (int c = 0; c < 16; c++) {
        int j = t + (c << 8);
        float v = (j >= i) ? row[j] : -INFINITY;
        vals[c] = v;
        m = fmaxf(m, v);
    }
    __shared__ float red[8];
#pragma unroll
    for (int o = 16; o > 0; o >>= 1) m = fmaxf(m, __shfl_xor_sync(0xffffffffu, m, o));
    if ((t & 31) == 0) red[t >> 5] = m;
    __syncthreads();
    float mm = red[0];
#pragma unroll
    for (int w = 1; w < 8; w++) mm = fmaxf(mm, red[w]);
    __syncthreads();

    float sum = 0.f;
#pragma unroll
    for (int c = 0; c < 16; c++) {
        float e = (vals[c] > -INFINITY) ? __expf(vals[c] - mm) : 0.f;
        vals[c] = e;
        sum += e;
    }
#pragma unroll
    for (int o = 16; o > 0; o >>= 1) sum += __shfl_xor_sync(0xffffffffu, sum, o);
    if ((t & 31) == 0) red[t >> 5] = sum;
    __syncthreads();
    float tot = 0.f;
#pragma unroll
    for (int w = 0; w < 8; w++) tot += red[w];
    const float inv = 1.0f / tot;

    const int rowstart = i & ~127;
    float* p = g_p + (size_t)i * SEQ;
#pragma unroll
    for (int c = 0; c < 16; c++) {
        int j = t + (c << 8);
        if (j >= i)             p[j] = tf32r(vals[c] * inv);
        else if (j >= rowstart) p[j] = 0.f;
    }
}

// ---------------------------------------------------------------------------
// PV: read = P @ V ; A = probs [s][s], B = V^T [d][s]; k starts at diagonal
// ---------------------------------------------------------------------------
__global__ __launch_bounds__(256) void gemm_pv_kernel(float* __restrict__ out)
{
    extern __shared__ char smem[];
    const int row0 = blockIdx.y * 128, col0 = blockIdx.x * 128;

    float acc[4][4][4];
#pragma unroll
    for (int i = 0; i < 4; i++)
#pragma unroll
        for (int j = 0; j < 4; j++)
#pragma unroll
            for (int q = 0; q < 4; q++) acc[i][j][q] = 0.f;

    gemm_mainloop(acc, smem, g_p, SEQ, row0, g_vt, SEQ, col0, row0, SEQ);

    GEMM_THREAD_COORDS();
#pragma unroll
    for (int mt = 0; mt < 4; mt++)
#pragma unroll
        for (int h = 0; h < 2; h++) {
            int m = row0 + wm + mt * 16 + r + 8 * h;
#pragma unroll
            for (int nt = 0; nt < 4; nt++) {
                int n = col0 + wn + nt * 8 + 2 * cc;
                float2 w = make_float2(acc[mt][nt][2 * h], acc[mt][nt][2 * h + 1]);
                *(float2*)&out[(size_t)m * OUTD + DIM + n] = w;
            }
        }
}

// ---------------------------------------------------------------------------
// conversions
// ---------------------------------------------------------------------------
__global__ __launch_bounds__(256) void conv_x_kernel(const float* __restrict__ x,
                                                     float* __restrict__ out)
{
    int idx = blockIdx.x * 256 + threadIdx.x;   // float4 index
    int r = idx >> 8;
    int c = (idx & 255) * 4;
    float4 v = *(const float4*)&x[(size_t)r * DIM + c];
    *(float4*)&out[(size_t)r * OUTD + c] = v;   // out[:, 0:1024] = x
    float4 w = make_float4(tf32r(v.x), tf32r(v.y), tf32r(v.z), tf32r(v.w));
    *(float4*)&g_x[(size_t)r * DIM + c] = w;
}

// transpose + tf32-round W [k][n] -> Wt [n][k] (slot z: 0=Q, 1=K, 2=V)
__global__ __launch_bounds__(256) void conv_w_kernel(const float* __restrict__ Wq,
                                                     const float* __restrict__ Wk,
                                                     const float* __restrict__ Wv)
{
    __shared__ float t[32][33];
    const int z = blockIdx.z;
    const float* W = (z == 0) ? Wq : (z == 1) ? Wk : Wv;
    const int n0 = blockIdx.x * 32, k0 = blockIdx.y * 32;
    const int tx = threadIdx.x & 31, ty = threadIdx.x >> 5;
#pragma unroll
    for (int i = 0; i < 4; i++) {
        int k = ty + i * 8;
        t[k][tx] = W[(size_t)(k0 + k) * DIM + n0 + tx];
    }
    __syncthreads();
    float* T = g_wt + (size_t)z * DIM * DIM;
#pragma unroll
    for (int i = 0; i < 4; i++) {
        int n = ty + i * 8;
        T[(size_t)(n0 + n) * DIM + k0 + tx] = tf32r(t[tx][n]);
    }
}

// ---------------------------------------------------------------------------
extern "C" void kernel_launch(void* const* d_in, const int* in_sizes, int n_in,
                              void* d_out, int out_size)
{
    const float* x  = (const float*)d_in[0];
    const float* Wk = (const float*)d_in[1];
    const float* bk = (const float*)d_in[2];
    const float* Wq = (const float*)d_in[3];
    const float* bq = (const float*)d_in[4];
    const float* Wv = (const float*)d_in[5];
    const float* bv = (const float*)d_in[6];
    float* out = (float*)d_out;

    cudaFuncSetAttribute(gemm_qkv_kernel,    cudaFuncAttributeMaxDynamicSharedMemorySize, SMEM_DYN);
    cudaFuncSetAttribute(gemm_scores_kernel, cudaFuncAttributeMaxDynamicSharedMemorySize, SMEM_DYN);
    cudaFuncSetAttribute(gemm_pv_kernel,     cudaFuncAttributeMaxDynamicSharedMemorySize, SMEM_DYN);

    conv_x_kernel<<<4096, 256>>>(x, out);
    conv_w_kernel<<<dim3(32, 32, 3), 256>>>(Wq, Wk, Wv);
    gemm_qkv_kernel<<<dim3(32, 32, 3), 256, SMEM_DYN>>>(bq, bk, bv);
    gemm_scores_kernel<<<dim3(32, 32), 256, SMEM_DYN>>>();
    softmax_kernel<<<SEQ, 256>>>();
    gemm_pv_kernel<<<dim3(8, 32), 256, SMEM_DYN>>>(out);
}

// round 4
// speedup vs baseline: 2.5878x; 1.1243x over previous
#include <cuda_runtime.h>
#include <math.h>
#include <stdint.h>

#define SEQ   4096
#define DIM   1024
#define OUTD  2048
#define SCALE 0.03125f   // 1/sqrt(1024)

#define PADW  36                       // 32 floats + 4 pad per smem row
#define BUF_B (128 * PADW * 4)         // one operand tile: 18432 B
#define STAGE (2 * BUF_B)              // A + B per stage: 36864 B
#define NSTG  4
#define SMEM_DYN (NSTG * STAGE)        // 147456 B

// ---------------------------------------------------------------------------
// scratch (__device__ globals; no allocations allowed)
// ---------------------------------------------------------------------------
__device__ float g_x [(size_t)SEQ * DIM];          // x, tf32-rounded
__device__ float g_wt[(size_t)3 * DIM * DIM];      // W^T (Q,K,V), tf32-rounded
__device__ float g_q [(size_t)SEQ * DIM];          // tf32-rounded
__device__ float g_k [(size_t)SEQ * DIM];          // tf32-rounded
__device__ float g_vt[(size_t)DIM * SEQ];          // V^T [d][s], tf32-rounded
__device__ float g_s [(size_t)SEQ * SEQ];          // scores fp32
__device__ float g_p [(size_t)SEQ * SEQ];          // probs, tf32-rounded

// ---------------------------------------------------------------------------
// helpers
// ---------------------------------------------------------------------------
__device__ __forceinline__ uint32_t smem_u32(const void* p) {
    uint32_t a;
    asm("{ .reg .u64 t; cvta.to.shared.u64 t, %1; cvt.u32.u64 %0, t; }" : "=r"(a) : "l"(p));
    return a;
}
__device__ __forceinline__ float tf32r(float x) {
    uint32_t u;
    asm("cvt.rna.tf32.f32 %0, %1;" : "=r"(u) : "f"(x));
    return __uint_as_float(u);
}
__device__ __forceinline__ void cp16(uint32_t s, const float* g) {
    asm volatile("{ .reg .u64 gg; cvta.to.global.u64 gg, %1;"
                 "  cp.async.cg.shared.global [%0], [gg], 16; }"
                 :: "r"(s), "l"(g));
}
#define CP_COMMIT() asm volatile("cp.async.commit_group;" ::: "memory")
#define CP_WAIT2()  asm volatile("cp.async.wait_group 2;"  ::: "memory")

__device__ __forceinline__ void mma8(float* d, const float* a, const float* b) {
    asm volatile(
        "mma.sync.aligned.m16n8k8.row.col.f32.tf32.tf32.f32 "
        "{%0,%1,%2,%3}, {%4,%5,%6,%7}, {%8,%9}, {%0,%1,%2,%3};"
        : "+f"(d[0]), "+f"(d[1]), "+f"(d[2]), "+f"(d[3])
        : "r"(__float_as_uint(a[0])), "r"(__float_as_uint(a[1])),
          "r"(__float_as_uint(a[2])), "r"(__float_as_uint(a[3])),
          "r"(__float_as_uint(b[0])), "r"(__float_as_uint(b[1])));
}

__device__ __forceinline__ void load_afrag(float d[4][4], const float* As,
                                           int wm, int r, int cc, int ks) {
#pragma unroll
    for (int mt = 0; mt < 4; mt++) {
        const float* p = As + (wm + mt * 16 + r) * PADW + ks * 8 + cc;
        d[mt][0] = p[0];
        d[mt][1] = p[8 * PADW];
        d[mt][2] = p[4];
        d[mt][3] = p[8 * PADW + 4];
    }
}
__device__ __forceinline__ void load_bfrag(float d[4][2], const float* Bs,
                                           int wn, int r, int cc, int ks) {
#pragma unroll
    for (int nt = 0; nt < 4; nt++) {
        const float* p = Bs + (wn + nt * 8 + r) * PADW + ks * 8 + cc;
        d[nt][0] = p[0];
        d[nt][1] = p[4];
    }
}

__device__ __forceinline__ void issue_chunk(uint32_t st,
    const float* __restrict__ Ag, int lda, int arow0,
    const float* __restrict__ Bg, int ldb, int brow0,
    int k0, int lm, int lq0)
{
#pragma unroll
    for (int q = 0; q < 4; q++) {
        cp16(st +         (lm * PADW + (lq0 + q) * 4) * 4,
             Ag + (size_t)(arow0 + lm) * lda + k0 + (lq0 + q) * 4);
        cp16(st + BUF_B + (lm * PADW + (lq0 + q) * 4) * 4,
             Bg + (size_t)(brow0 + lm) * ldb + k0 + (lq0 + q) * 4);
    }
}

// ---------------------------------------------------------------------------
// 4-stage mainloop: acc[4][4][4] += A[128,K] * B[128,K]^T over k in [kbeg,kend)
// A: [m][k] row-major (lda), rows arow0.. ; B: [n][k] row-major (ldb), rows brow0..
// warp layout: 8 warps = 2(m) x 4(n); warp tile 64x32; m16n8k8 tf32, 4x4 tiles
// One __syncthreads per chunk; fragment register double-buffering over ks.
// ---------------------------------------------------------------------------
__device__ __forceinline__ void gemm_mainloop(
    float acc[4][4][4], char* smem,
    const float* __restrict__ Ag, int lda, int arow0,
    const float* __restrict__ Bg, int ldb, int brow0,
    int kbeg, int kend)
{
    const int tid  = threadIdx.x;
    const int wid  = tid >> 5, lane = tid & 31;
    const int wm   = (wid & 1) * 64;
    const int wn   = (wid >> 1) * 32;
    const int r    = lane >> 2, cc = lane & 3;
    const uint32_t sA = smem_u32(smem);
    const int nch  = (kend - kbeg) >> 5;

    const int lm  = tid >> 1;            // loader: row (2 threads/row)
    const int lq0 = (tid & 1) * 4;       // loader: 16B-chunk start

    // prologue: fill 3 stages
#pragma unroll
    for (int c = 0; c < 3; c++) {
        if (c < nch)
            issue_chunk(sA + c * STAGE, Ag, lda, arow0, Bg, ldb, brow0,
                        kbeg + c * 32, lm, lq0);
        CP_COMMIT();
    }

    for (int c = 0; c < nch; c++) {
        CP_WAIT2();
        __syncthreads();
        const float* As = (const float*)(smem + (c & 3) * STAGE);
        const float* Bs = (const float*)(smem + (c & 3) * STAGE + BUF_B);

        float af[2][4][4], bf[2][4][2];
        load_afrag(af[0], As, wm, r, cc, 0);
        load_bfrag(bf[0], Bs, wn, r, cc, 0);
#pragma unroll
        for (int ks = 0; ks < 4; ks++) {
            const int cur = ks & 1;
            if (ks < 3) {
                load_afrag(af[cur ^ 1], As, wm, r, cc, ks + 1);
                load_bfrag(bf[cur ^ 1], Bs, wn, r, cc, ks + 1);
            }
#pragma unroll
            for (int mt = 0; mt < 4; mt++)
#pragma unroll
                for (int nt = 0; nt < 4; nt++)
                    mma8(acc[mt][nt], af[cur][mt], bf[cur][nt]);
        }
        // refill the stage consumed at c-1 with chunk c+3 (safe: barrier above
        // guaranteed all warps finished reading stage (c-1)&3)
        if (c + 3 < nch)
            issue_chunk(sA + ((c + 3) & 3) * STAGE, Ag, lda, arow0, Bg, ldb, brow0,
                        kbeg + (c + 3) * 32, lm, lq0);
        CP_COMMIT();
    }
}

#define GEMM_THREAD_COORDS()                                   \
    const int tid = threadIdx.x;                               \
    const int wid = tid >> 5, lane = tid & 31;                 \
    const int wm = (wid & 1) * 64, wn = (wid >> 1) * 32;       \
    const int r = lane >> 2, cc = lane & 3;

#define ZERO_ACC(acc)                                          \
    float acc[4][4][4];                                        \
    _Pragma("unroll")                                          \
    for (int i = 0; i < 4; i++)                                \
        _Pragma("unroll")                                      \
        for (int j = 0; j < 4; j++)                            \
            _Pragma("unroll")                                  \
            for (int q = 0; q < 4; q++) acc[i][j][q] = 0.f;

// ---------------------------------------------------------------------------
// QKV: z=0: Q = x@WqT' + bq ; z=1: K ; z=2: V^T = Wvt @ x^T + bv(row)
// grid (8, 32, 3); for z==2 the 8-wide axis is the M (row) axis.
// ---------------------------------------------------------------------------
__global__ __launch_bounds__(256) void gemm_qkv_kernel(
    const float* __restrict__ bq, const float* __restrict__ bk, const float* __restrict__ bv)
{
    const int z = blockIdx.z;
    extern __shared__ char smem[];
    const int row0 = (z == 2 ? blockIdx.x : blockIdx.y) * 128;
    const int col0 = (z == 2 ? blockIdx.y : blockIdx.x) * 128;

    ZERO_ACC(acc);

    const float *Ag, *Bg, *bias;
    if (z == 0)      { Ag = g_x;                  Bg = g_wt;             bias = bq; }
    else if (z == 1) { Ag = g_x;                  Bg = g_wt + DIM * DIM; bias = bk; }
    else             { Ag = g_wt + 2 * DIM * DIM; Bg = g_x;              bias = bv; }

    gemm_mainloop(acc, smem, Ag, DIM, row0, Bg, DIM, col0, 0, DIM);

    GEMM_THREAD_COORDS();
    float* dst; size_t ld;
    if (z == 0)      { dst = g_q;  ld = DIM; }
    else if (z == 1) { dst = g_k;  ld = DIM; }
    else             { dst = g_vt; ld = SEQ; }

#pragma unroll
    for (int mt = 0; mt < 4; mt++)
#pragma unroll
        for (int h = 0; h < 2; h++) {
            int m = row0 + wm + mt * 16 + r + 8 * h;
            float brow = (z == 2) ? bias[m] : 0.f;
#pragma unroll
            for (int nt = 0; nt < 4; nt++) {
                int n = col0 + wn + nt * 8 + 2 * cc;
                float v0 = acc[mt][nt][2 * h + 0] + ((z == 2) ? brow : bias[n]);
                float v1 = acc[mt][nt][2 * h + 1] + ((z == 2) ? brow : bias[n + 1]);
                float2 w = make_float2(tf32r(v0), tf32r(v1));
                *(float2*)&dst[(size_t)m * ld + n] = w;
            }
        }
}

// ---------------------------------------------------------------------------
// scores: S = SCALE * Q K^T, upper-triangular tiles only (528 blocks)
// ---------------------------------------------------------------------------
__global__ __launch_bounds__(256) void gemm_scores_kernel()
{
    // triangular decode: block -> (bi, bj) with bj >= bi
    int bi = 0, rem = blockIdx.x;
    while (rem >= 32 - bi) { rem -= 32 - bi; bi++; }
    const int bj = bi + rem;

    extern __shared__ char smem[];
    const int row0 = bi * 128, col0 = bj * 128;

    ZERO_ACC(acc);
    gemm_mainloop(acc, smem, g_q, DIM, row0, g_k, DIM, col0, 0, DIM);

    GEMM_THREAD_COORDS();
#pragma unroll
    for (int mt = 0; mt < 4; mt++)
#pragma unroll
        for (int h = 0; h < 2; h++) {
            int m = row0 + wm + mt * 16 + r + 8 * h;
#pragma unroll
            for (int nt = 0; nt < 4; nt++) {
                int n = col0 + wn + nt * 8 + 2 * cc;
                float2 w = make_float2(acc[mt][nt][2 * h] * SCALE,
                                       acc[mt][nt][2 * h + 1] * SCALE);
                *(float2*)&g_s[(size_t)m * SEQ + n] = w;
            }
        }
}

// ---------------------------------------------------------------------------
// softmax over j >= i; writes tf32-rounded probs, zero strip in diagonal tile
// ---------------------------------------------------------------------------
__global__ __launch_bounds__(256) void softmax_kernel()
{
    const int i = blockIdx.x;
    const int t = threadIdx.x;
    const float* row = g_s + (size_t)i * SEQ;

    float vals[16];
    float m = -INFINITY;
#pragma unroll
    for (int c = 0; c < 16; c++) {
        int j = t + (c << 8);
        float v = (j >= i) ? row[j] : -INFINITY;
        vals[c] = v;
        m = fmaxf(m, v);
    }
    __shared__ float red[8];
#pragma unroll
    for (int o = 16; o > 0; o >>= 1) m = fmaxf(m, __shfl_xor_sync(0xffffffffu, m, o));
    if ((t & 31) == 0) red[t >> 5] = m;
    __syncthreads();
    float mm = red[0];
#pragma unroll
    for (int w = 1; w < 8; w++) mm = fmaxf(mm, red[w]);
    __syncthreads();

    float sum = 0.f;
#pragma unroll
    for (int c = 0; c < 16; c++) {
        float e = (vals[c] > -INFINITY) ? __expf(vals[c] - mm) : 0.f;
        vals[c] = e;
        sum += e;
    }
#pragma unroll
    for (int o = 16; o > 0; o >>= 1) sum += __shfl_xor_sync(0xffffffffu, sum, o);
    if ((t & 31) == 0) red[t >> 5] = sum;
    __syncthreads();
    float tot = 0.f;
#pragma unroll
    for (int w = 0; w < 8; w++) tot += red[w];
    const float inv = 1.0f / tot;

    const int rowstart = i & ~127;
    float* p = g_p + (size_t)i * SEQ;
#pragma unroll
    for (int c = 0; c < 16; c++) {
        int j = t + (c << 8);
        if (j >= i)             p[j] = tf32r(vals[c] * inv);
        else if (j >= rowstart) p[j] = 0.f;
    }
}

// ---------------------------------------------------------------------------
// PV: read = P @ V ; A = probs [s][s], B = V^T [d][s]; k starts at diagonal
// ---------------------------------------------------------------------------
__global__ __launch_bounds__(256) void gemm_pv_kernel(float* __restrict__ out)
{
    extern __shared__ char smem[];
    const int row0 = blockIdx.y * 128, col0 = blockIdx.x * 128;

    ZERO_ACC(acc);
    gemm_mainloop(acc, smem, g_p, SEQ, row0, g_vt, SEQ, col0, row0, SEQ);

    GEMM_THREAD_COORDS();
#pragma unroll
    for (int mt = 0; mt < 4; mt++)
#pragma unroll
        for (int h = 0; h < 2; h++) {
            int m = row0 + wm + mt * 16 + r + 8 * h;
#pragma unroll
            for (int nt = 0; nt < 4; nt++) {
                int n = col0 + wn + nt * 8 + 2 * cc;
                float2 w = make_float2(acc[mt][nt][2 * h], acc[mt][nt][2 * h + 1]);
                *(float2*)&out[(size_t)m * OUTD + DIM + n] = w;
            }
        }
}

// ---------------------------------------------------------------------------
// conversions
// ---------------------------------------------------------------------------
__global__ __launch_bounds__(256) void conv_x_kernel(const float* __restrict__ x,
                                                     float* __restrict__ out)
{
    int idx = blockIdx.x * 256 + threadIdx.x;   // float4 index
    int r = idx >> 8;
    int c = (idx & 255) * 4;
    float4 v = *(const float4*)&x[(size_t)r * DIM + c];
    *(float4*)&out[(size_t)r * OUTD + c] = v;   // out[:, 0:1024] = x
    float4 w = make_float4(tf32r(v.x), tf32r(v.y), tf32r(v.z), tf32r(v.w));
    *(float4*)&g_x[(size_t)r * DIM + c] = w;
}

// transpose + tf32-round W [k][n] -> Wt [n][k] (slot z: 0=Q, 1=K, 2=V)
__global__ __launch_bounds__(256) void conv_w_kernel(const float* __restrict__ Wq,
                                                     const float* __restrict__ Wk,
                                                     const float* __restrict__ Wv)
{
    __shared__ float t[32][33];
    const int z = blockIdx.z;
    const float* W = (z == 0) ? Wq : (z == 1) ? Wk : Wv;
    const int n0 = blockIdx.x * 32, k0 = blockIdx.y * 32;
    const int tx = threadIdx.x & 31, ty = threadIdx.x >> 5;
#pragma unroll
    for (int i = 0; i < 4; i++) {
        int k = ty + i * 8;
        t[k][tx] = W[(size_t)(k0 + k) * DIM + n0 + tx];
    }
    __syncthreads();
    float* T = g_wt + (size_t)z * DIM * DIM;
#pragma unroll
    for (int i = 0; i < 4; i++) {
        int n = ty + i * 8;
        T[(size_t)(n0 + n) * DIM + k0 + tx] = tf32r(t[tx][n]);
    }
}

// ---------------------------------------------------------------------------
extern "C" void kernel_launch(void* const* d_in, const int* in_sizes, int n_in,
                              void* d_out, int out_size)
{
    const float* x  = (const float*)d_in[0];
    const float* Wk = (const float*)d_in[1];
    const float* bk = (const float*)d_in[2];
    const float* Wq = (const float*)d_in[3];
    const float* bq = (const float*)d_in[4];
    const float* Wv = (const float*)d_in[5];
    const float* bv = (const float*)d_in[6];
    float* out = (float*)d_out;

    cudaFuncSetAttribute(gemm_qkv_kernel,    cudaFuncAttributeMaxDynamicSharedMemorySize, SMEM_DYN);
    cudaFuncSetAttribute(gemm_scores_kernel, cudaFuncAttributeMaxDynamicSharedMemorySize, SMEM_DYN);
    cudaFuncSetAttribute(gemm_pv_kernel,     cudaFuncAttributeMaxDynamicSharedMemorySize, SMEM_DYN);

    conv_x_kernel<<<4096, 256>>>(x, out);
    conv_w_kernel<<<dim3(32, 32, 3), 256>>>(Wq, Wk, Wv);
    gemm_qkv_kernel<<<dim3(8, 32, 3), 256, SMEM_DYN>>>(bq, bk, bv);
    gemm_scores_kernel<<<528, 256, SMEM_DYN>>>();
    softmax_kernel<<<SEQ, 256>>>();
    gemm_pv_kernel<<<dim3(8, 32), 256, SMEM_DYN>>>(out);
}